// round 10
// baseline (speedup 1.0000x reference)
#include <cuda_runtime.h>

// spu(z) = z^2 - 0.5 (z>=0), sigmoid(-z) - 1 (z<0); dspu analogous.
// Elementwise over d = 16,777,216 fp32; 192 MiB in + 192 MiB out -> HBM stream.
// R9 = R5 exactly (best: 56.0us kernel, DRAM 78.7%, regs 40 -> 6 blocks/SM)
//      + gentle reg cap __launch_bounds__(256, 7): 36 regs -> 7 blocks/SM
//        (87.5% theoretical occ). R6's 32-reg cap spilled; 36 should not.

__device__ __forceinline__ float tanh_half(float z) {
    float t;
    asm("tanh.approx.f32 %0, %1;" : "=f"(t) : "f"(0.5f * z));
    return t;
}

// spu(z) with one MUFU: t = tanh(z/2); negative branch = -0.5 - 0.5*t
__device__ __forceinline__ float spu_f(float z) {
    float t = tanh_half(z);
    float neg = fmaf(-0.5f, t, -0.5f);       // sigmoid(-z) - 1
    float pos = fmaf(z, z, -0.5f);
    return (z >= 0.0f) ? pos : neg;
}

__device__ __forceinline__ void spu_elem(float x, float l, float u,
                                         float& xo, float& lo, float& uo) {
    // p = clip(u - (|l|+|u|)/2, l, u)
    float p = u - 0.5f * (fabsf(l) + fabsf(u));
    p = fminf(fmaxf(p, l), u);

    float sl = spu_f(l);
    float su = spu_f(u);

    // tangent at p, one tanh shared by sp and dspu(p):
    //   sp  (p<0) = -0.5 - 0.5*t
    //   dspu(p<0) = 0.25*t^2 - 0.25
    float tp = tanh_half(p);
    bool  ppos = (p >= 0.0f);
    float sp        = ppos ? fmaf(p, p, -0.5f) : fmaf(-0.5f, tp, -0.5f);
    float tan_slope = ppos ? (2.0f * p)        : fmaf(0.25f * tp, tp, -0.25f);
    float tan_int   = sp - p * tan_slope;

    // chord through (l, sl), (u, su)
    float du = (u != l) ? (u - l) : 1.0f;
    float chord_slope = __fdividef(su - sl, du);
    float chord_int   = sl - chord_slope * l;

    // line through (l, sl) and (0, -0.5)
    float dl = (l != 0.0f) ? (-l) : 1.0f;
    float zl_slope = __fdividef(-0.5f - sl, dl);

    bool upos = (u > 0.0f);

    float lb_slope = upos ? (ppos ? tan_slope : zl_slope) : chord_slope;
    float lb_int   = upos ? (ppos ? tan_int   : -0.5f   ) : chord_int;
    float ub_slope = upos ? chord_slope : tan_slope;
    float ub_int   = upos ? chord_int   : tan_int;

    lo = fmaf((lb_slope > 0.0f) ? l : u, lb_slope, lb_int);
    uo = fmaf((ub_slope > 0.0f) ? u : l, ub_slope, ub_int);
    xo = spu_f(x);
}

__global__ __launch_bounds__(256, 7)
void spu_transformer_kernel(const float4* __restrict__ x,
                            const float4* __restrict__ l,
                            const float4* __restrict__ u,
                            float4* __restrict__ x_out,
                            float4* __restrict__ l_out,
                            float4* __restrict__ u_out,
                            int n4) {
    int i = blockIdx.x * blockDim.x + threadIdx.x;
    if (i >= n4) return;

    float4 xv = x[i];
    float4 lv = l[i];
    float4 uv = u[i];

    float4 xo, lo, uo;
    spu_elem(xv.x, lv.x, uv.x, xo.x, lo.x, uo.x);
    spu_elem(xv.y, lv.y, uv.y, xo.y, lo.y, uo.y);
    spu_elem(xv.z, lv.z, uv.z, xo.z, lo.z, uo.z);
    spu_elem(xv.w, lv.w, uv.w, xo.w, lo.w, uo.w);

    x_out[i] = xo;
    l_out[i] = lo;
    u_out[i] = uo;
}

extern "C" void kernel_launch(void* const* d_in, const int* in_sizes, int n_in,
                              void* d_out, int out_size) {
    const float* x = (const float*)d_in[0];
    const float* l = (const float*)d_in[1];
    const float* u = (const float*)d_in[2];
    float* out = (float*)d_out;

    int n = in_sizes[0];            // 16,777,216
    int n4 = n >> 2;                // 4,194,304 float4s

    float* x_out = out;
    float* l_out = out + (size_t)n;
    float* u_out = out + 2 * (size_t)n;

    int threads = 256;
    int blocks = (n4 + threads - 1) / threads;   // 16384
    spu_transformer_kernel<<<blocks, threads>>>(
        (const float4*)x, (const float4*)l, (const float4*)u,
        (float4*)x_out, (float4*)l_out, (float4*)u_out, n4);
}

// round 11
// speedup vs baseline: 1.0025x; 1.0025x over previous
#include <cuda_runtime.h>

// spu(z) = z^2 - 0.5 (z>=0), sigmoid(-z) - 1 (z<0); dspu analogous.
// Elementwise over d = 16,777,216 fp32; 192 MiB in + 192 MiB out -> HBM stream.
// R10 = R5 math exactly (tanh.approx single-MUFU sigmoid, 1 float4/thread,
//       natural 40 regs — NO reg cap, both caps spilled) with 128-thread blocks:
//       2x the CTAs (32768) for finer GigaThread dispatch + smaller tails.

__device__ __forceinline__ float tanh_half(float z) {
    float t;
    asm("tanh.approx.f32 %0, %1;" : "=f"(t) : "f"(0.5f * z));
    return t;
}

// spu(z) with one MUFU: t = tanh(z/2); negative branch = -0.5 - 0.5*t
__device__ __forceinline__ float spu_f(float z) {
    float t = tanh_half(z);
    float neg = fmaf(-0.5f, t, -0.5f);       // sigmoid(-z) - 1
    float pos = fmaf(z, z, -0.5f);
    return (z >= 0.0f) ? pos : neg;
}

__device__ __forceinline__ void spu_elem(float x, float l, float u,
                                         float& xo, float& lo, float& uo) {
    // p = clip(u - (|l|+|u|)/2, l, u)
    float p = u - 0.5f * (fabsf(l) + fabsf(u));
    p = fminf(fmaxf(p, l), u);

    float sl = spu_f(l);
    float su = spu_f(u);

    // tangent at p, one tanh shared by sp and dspu(p):
    //   sp  (p<0) = -0.5 - 0.5*t
    //   dspu(p<0) = 0.25*t^2 - 0.25
    float tp = tanh_half(p);
    bool  ppos = (p >= 0.0f);
    float sp        = ppos ? fmaf(p, p, -0.5f) : fmaf(-0.5f, tp, -0.5f);
    float tan_slope = ppos ? (2.0f * p)        : fmaf(0.25f * tp, tp, -0.25f);
    float tan_int   = sp - p * tan_slope;

    // chord through (l, sl), (u, su)
    float du = (u != l) ? (u - l) : 1.0f;
    float chord_slope = __fdividef(su - sl, du);
    float chord_int   = sl - chord_slope * l;

    // line through (l, sl) and (0, -0.5)
    float dl = (l != 0.0f) ? (-l) : 1.0f;
    float zl_slope = __fdividef(-0.5f - sl, dl);

    bool upos = (u > 0.0f);

    float lb_slope = upos ? (ppos ? tan_slope : zl_slope) : chord_slope;
    float lb_int   = upos ? (ppos ? tan_int   : -0.5f   ) : chord_int;
    float ub_slope = upos ? chord_slope : tan_slope;
    float ub_int   = upos ? chord_int   : tan_int;

    lo = fmaf((lb_slope > 0.0f) ? l : u, lb_slope, lb_int);
    uo = fmaf((ub_slope > 0.0f) ? u : l, ub_slope, ub_int);
    xo = spu_f(x);
}

__global__ __launch_bounds__(128)
void spu_transformer_kernel(const float4* __restrict__ x,
                            const float4* __restrict__ l,
                            const float4* __restrict__ u,
                            float4* __restrict__ x_out,
                            float4* __restrict__ l_out,
                            float4* __restrict__ u_out,
                            int n4) {
    int i = blockIdx.x * blockDim.x + threadIdx.x;
    if (i >= n4) return;

    float4 xv = x[i];
    float4 lv = l[i];
    float4 uv = u[i];

    float4 xo, lo, uo;
    spu_elem(xv.x, lv.x, uv.x, xo.x, lo.x, uo.x);
    spu_elem(xv.y, lv.y, uv.y, xo.y, lo.y, uo.y);
    spu_elem(xv.z, lv.z, uv.z, xo.z, lo.z, uo.z);
    spu_elem(xv.w, lv.w, uv.w, xo.w, lo.w, uo.w);

    x_out[i] = xo;
    l_out[i] = lo;
    u_out[i] = uo;
}

extern "C" void kernel_launch(void* const* d_in, const int* in_sizes, int n_in,
                              void* d_out, int out_size) {
    const float* x = (const float*)d_in[0];
    const float* l = (const float*)d_in[1];
    const float* u = (const float*)d_in[2];
    float* out = (float*)d_out;

    int n = in_sizes[0];            // 16,777,216
    int n4 = n >> 2;                // 4,194,304 float4s

    float* x_out = out;
    float* l_out = out + (size_t)n;
    float* u_out = out + 2 * (size_t)n;

    int threads = 128;
    int blocks = (n4 + threads - 1) / threads;   // 32768
    spu_transformer_kernel<<<blocks, threads>>>(
        (const float4*)x, (const float4*)l, (const float4*)u,
        (float4*)x_out, (float4*)l_out, (float4*)u_out, n4);
}

// round 12
// speedup vs baseline: 1.0158x; 1.0133x over previous
#include <cuda_runtime.h>

// spu(z) = z^2 - 0.5 (z>=0), sigmoid(-z) - 1 (z<0); dspu analogous.
// Elementwise over d = 16,777,216 fp32; 192 MiB in + 192 MiB out -> HBM stream.
// R11 = R5 (champion: tanh.approx single-MUFU sigmoid, 1 float4/thread, 256 thr,
//       natural regs) + exact-grid launch: 16384 blocks x 256 thr x 1 float4
//       == 4,194,304 float4s exactly -> no bounds check, no n4 param, loads
//       issue with zero predicate/branch overhead in the prologue.

__device__ __forceinline__ float tanh_half(float z) {
    float t;
    asm("tanh.approx.f32 %0, %1;" : "=f"(t) : "f"(0.5f * z));
    return t;
}

// spu(z) with one MUFU: t = tanh(z/2); negative branch = -0.5 - 0.5*t
__device__ __forceinline__ float spu_f(float z) {
    float t = tanh_half(z);
    float neg = fmaf(-0.5f, t, -0.5f);       // sigmoid(-z) - 1
    float pos = fmaf(z, z, -0.5f);
    return (z >= 0.0f) ? pos : neg;
}

__device__ __forceinline__ void spu_elem(float x, float l, float u,
                                         float& xo, float& lo, float& uo) {
    // p = clip(u - (|l|+|u|)/2, l, u)
    float p = u - 0.5f * (fabsf(l) + fabsf(u));
    p = fminf(fmaxf(p, l), u);

    float sl = spu_f(l);
    float su = spu_f(u);

    // tangent at p, one tanh shared by sp and dspu(p):
    //   sp  (p<0) = -0.5 - 0.5*t
    //   dspu(p<0) = 0.25*t^2 - 0.25
    float tp = tanh_half(p);
    bool  ppos = (p >= 0.0f);
    float sp        = ppos ? fmaf(p, p, -0.5f) : fmaf(-0.5f, tp, -0.5f);
    float tan_slope = ppos ? (2.0f * p)        : fmaf(0.25f * tp, tp, -0.25f);
    float tan_int   = sp - p * tan_slope;

    // chord through (l, sl), (u, su)
    float du = (u != l) ? (u - l) : 1.0f;
    float chord_slope = __fdividef(su - sl, du);
    float chord_int   = sl - chord_slope * l;

    // line through (l, sl) and (0, -0.5)
    float dl = (l != 0.0f) ? (-l) : 1.0f;
    float zl_slope = __fdividef(-0.5f - sl, dl);

    bool upos = (u > 0.0f);

    float lb_slope = upos ? (ppos ? tan_slope : zl_slope) : chord_slope;
    float lb_int   = upos ? (ppos ? tan_int   : -0.5f   ) : chord_int;
    float ub_slope = upos ? chord_slope : tan_slope;
    float ub_int   = upos ? chord_int   : tan_int;

    lo = fmaf((lb_slope > 0.0f) ? l : u, lb_slope, lb_int);
    uo = fmaf((ub_slope > 0.0f) ? u : l, ub_slope, ub_int);
    xo = spu_f(x);
}

__global__ __launch_bounds__(256)
void spu_transformer_kernel(const float4* __restrict__ x,
                            const float4* __restrict__ l,
                            const float4* __restrict__ u,
                            float4* __restrict__ x_out,
                            float4* __restrict__ l_out,
                            float4* __restrict__ u_out) {
    int i = blockIdx.x * blockDim.x + threadIdx.x;   // exact grid: no bounds check

    float4 xv = x[i];
    float4 lv = l[i];
    float4 uv = u[i];

    float4 xo, lo, uo;
    spu_elem(xv.x, lv.x, uv.x, xo.x, lo.x, uo.x);
    spu_elem(xv.y, lv.y, uv.y, xo.y, lo.y, uo.y);
    spu_elem(xv.z, lv.z, uv.z, xo.z, lo.z, uo.z);
    spu_elem(xv.w, lv.w, uv.w, xo.w, lo.w, uo.w);

    x_out[i] = xo;
    l_out[i] = lo;
    u_out[i] = uo;
}

extern "C" void kernel_launch(void* const* d_in, const int* in_sizes, int n_in,
                              void* d_out, int out_size) {
    const float* x = (const float*)d_in[0];
    const float* l = (const float*)d_in[1];
    const float* u = (const float*)d_in[2];
    float* out = (float*)d_out;

    int n = in_sizes[0];            // 16,777,216
    int n4 = n >> 2;                // 4,194,304 float4s

    float* x_out = out;
    float* l_out = out + (size_t)n;
    float* u_out = out + 2 * (size_t)n;

    int threads = 256;
    int blocks = n4 / threads;      // 16384, exact (n4 % 256 == 0)
    spu_transformer_kernel<<<blocks, threads>>>(
        (const float4*)x, (const float4*)l, (const float4*)u,
        (float4*)x_out, (float4*)l_out, (float4*)u_out);
}

// round 13
// speedup vs baseline: 1.0284x; 1.0124x over previous
#include <cuda_runtime.h>

// spu(z) = z^2 - 0.5 (z>=0), sigmoid(-z) - 1 (z<0); dspu analogous.
// Elementwise over d = 16,777,216 fp32; 192 MiB in + 192 MiB out -> HBM stream.
// FINAL (== R5, the measured champion: 56.0us kernel / 61.9us bench, DRAM 78.7%,
// 6.24 TB/s). Config: 1 float4/thread fully coalesced, 256-thread blocks, exact
// 16384-block grid, natural register allocation, single-MUFU sigmoid via
// tanh.approx:  sigmoid(-z) = 0.5 - 0.5*tanh(z/2)
//               s - 1       = -0.5 - 0.5*t
//               -s*(1-s)    = 0.25*t^2 - 0.25     (t = tanh(z/2))
// Levers tested and rejected: deeper per-thread MLP, reg caps (spill), persistent
// grid, streaming cache hints, 128-thread blocks — all neutral or regressions.

__device__ __forceinline__ float tanh_half(float z) {
    float t;
    asm("tanh.approx.f32 %0, %1;" : "=f"(t) : "f"(0.5f * z));
    return t;
}

// spu(z) with one MUFU: t = tanh(z/2); negative branch = -0.5 - 0.5*t
__device__ __forceinline__ float spu_f(float z) {
    float t = tanh_half(z);
    float neg = fmaf(-0.5f, t, -0.5f);       // sigmoid(-z) - 1
    float pos = fmaf(z, z, -0.5f);
    return (z >= 0.0f) ? pos : neg;
}

__device__ __forceinline__ void spu_elem(float x, float l, float u,
                                         float& xo, float& lo, float& uo) {
    // p = clip(u - (|l|+|u|)/2, l, u)
    float p = u - 0.5f * (fabsf(l) + fabsf(u));
    p = fminf(fmaxf(p, l), u);

    float sl = spu_f(l);
    float su = spu_f(u);

    // tangent at p, one tanh shared by sp and dspu(p):
    //   sp  (p<0) = -0.5 - 0.5*t
    //   dspu(p<0) = 0.25*t^2 - 0.25
    float tp = tanh_half(p);
    bool  ppos = (p >= 0.0f);
    float sp        = ppos ? fmaf(p, p, -0.5f) : fmaf(-0.5f, tp, -0.5f);
    float tan_slope = ppos ? (2.0f * p)        : fmaf(0.25f * tp, tp, -0.25f);
    float tan_int   = sp - p * tan_slope;

    // chord through (l, sl), (u, su)
    float du = (u != l) ? (u - l) : 1.0f;
    float chord_slope = __fdividef(su - sl, du);
    float chord_int   = sl - chord_slope * l;

    // line through (l, sl) and (0, -0.5)
    float dl = (l != 0.0f) ? (-l) : 1.0f;
    float zl_slope = __fdividef(-0.5f - sl, dl);

    bool upos = (u > 0.0f);

    float lb_slope = upos ? (ppos ? tan_slope : zl_slope) : chord_slope;
    float lb_int   = upos ? (ppos ? tan_int   : -0.5f   ) : chord_int;
    float ub_slope = upos ? chord_slope : tan_slope;
    float ub_int   = upos ? chord_int   : tan_int;

    lo = fmaf((lb_slope > 0.0f) ? l : u, lb_slope, lb_int);
    uo = fmaf((ub_slope > 0.0f) ? u : l, ub_slope, ub_int);
    xo = spu_f(x);
}

__global__ __launch_bounds__(256)
void spu_transformer_kernel(const float4* __restrict__ x,
                            const float4* __restrict__ l,
                            const float4* __restrict__ u,
                            float4* __restrict__ x_out,
                            float4* __restrict__ l_out,
                            float4* __restrict__ u_out,
                            int n4) {
    int i = blockIdx.x * blockDim.x + threadIdx.x;
    if (i >= n4) return;

    float4 xv = x[i];
    float4 lv = l[i];
    float4 uv = u[i];

    float4 xo, lo, uo;
    spu_elem(xv.x, lv.x, uv.x, xo.x, lo.x, uo.x);
    spu_elem(xv.y, lv.y, uv.y, xo.y, lo.y, uo.y);
    spu_elem(xv.z, lv.z, uv.z, xo.z, lo.z, uo.z);
    spu_elem(xv.w, lv.w, uv.w, xo.w, lo.w, uo.w);

    x_out[i] = xo;
    l_out[i] = lo;
    u_out[i] = uo;
}

extern "C" void kernel_launch(void* const* d_in, const int* in_sizes, int n_in,
                              void* d_out, int out_size) {
    const float* x = (const float*)d_in[0];
    const float* l = (const float*)d_in[1];
    const float* u = (const float*)d_in[2];
    float* out = (float*)d_out;

    int n = in_sizes[0];            // 16,777,216
    int n4 = n >> 2;                // divisible by 4

    float* x_out = out;
    float* l_out = out + (size_t)n;
    float* u_out = out + 2 * (size_t)n;

    int threads = 256;
    int blocks = (n4 + threads - 1) / threads;   // 16384
    spu_transformer_kernel<<<blocks, threads>>>(
        (const float4*)x, (const float4*)l, (const float4*)u,
        (float4*)x_out, (float4*)l_out, (float4*)u_out, n4);
}